// round 13
// baseline (speedup 1.0000x reference)
#include <cuda_runtime.h>
#include <math.h>
#include <stdint.h>
#include <string.h>

#define BB 64
#define SS 40
#define TD 39
#define EE 256
#define UU 1024
#define VV 8192
#define G3 3072

// Scratch (device globals; no allocation allowed)
static __device__ float g_gxe[BB * SS * G3];      // encoder x@Wx + b0
static __device__ float g_gxd[BB * TD * G3];      // decoder xt@Wx_bot + b0
static __device__ float g_enc_out[BB * SS * UU];  // encoder hidden sequence
static __device__ float g_P[BB * SS * G3];        // enc_out @ dec_Wx[:U]
static __device__ float g_hdec[BB * TD * UU];     // decoder hidden per step
static __device__ unsigned g_bar[4];              // [cnt0, rel0, cnt1, rel1]

// ---------------------------------------------------------------------------
__device__ __forceinline__ float2 fma2(float2 a, float2 b, float2 c) {
    unsigned long long ua, ub, uc;
    memcpy(&ua, &a, 8); memcpy(&ub, &b, 8); memcpy(&uc, &c, 8);
    asm("fma.rn.f32x2 %0, %1, %2, %0;" : "+l"(uc) : "l"(ua), "l"(ub));
    float2 r; memcpy(&r, &uc, 8);
    return r;
}

__device__ __forceinline__ float sigmoidf_(float x) {
    return 1.0f / (1.0f + expf(-x));
}

__device__ __forceinline__ uint32_t f2tf32(float x) {
    uint32_t r;
    asm("cvt.rna.tf32.f32 %0, %1;" : "=r"(r) : "f"(x));
    return r;
}

__device__ __forceinline__ void mma4(float c[4], const uint4& a,
                                     uint32_t b0, uint32_t b1) {
    asm("mma.sync.aligned.m16n8k8.row.col.f32.tf32.tf32.f32 "
        "{%0,%1,%2,%3},{%4,%5,%6,%7},{%8,%9},{%0,%1,%2,%3};"
        : "+f"(c[0]), "+f"(c[1]), "+f"(c[2]), "+f"(c[3])
        : "r"(a.x), "r"(a.y), "r"(a.z), "r"(a.w), "r"(b0), "r"(b1));
}

// ---------------------------------------------------------------------------
// fp32 GEMM (scalar f32x2 path) — step 1 only (feeds the recurrence).
// ---------------------------------------------------------------------------
__global__ __launch_bounds__(256, 2) void gemm_f32(
    const float* __restrict__ A,
    const float* __restrict__ emb, const int* __restrict__ idx,
    int idxTT, int idxStride, int lda,
    const float* __restrict__ W, int ldw,
    const float* __restrict__ bias,
    float* __restrict__ C, int M, int N, int K)
{
    __shared__ __align__(16) float As[2][8][128];
    __shared__ __align__(16) float Ws[2][8][128];

    const int tid = threadIdx.x;
    const int bm = blockIdx.y * 128;
    const int bn = blockIdx.x * 128;

    const int arow_l = tid & 127;
    const int akh    = tid >> 7;
    int mload = bm + arow_l;
    if (mload >= M) mload = M - 1;
    const float* arow;
    if (emb) {
        int r = idx[(mload / idxTT) * idxStride + (mload % idxTT)];
        arow = emb + (size_t)r * lda;
    } else {
        arow = A + (size_t)mload * lda;
    }

    const int wk = tid >> 5;
    const int wn = (tid & 31) * 4;
    const float* wptr = W + (size_t)wk * ldw + bn + wn;

    const int tx = tid & 15, ty = tid >> 4;
    const int r0 = ty * 8, c0 = tx * 8;

    float2 acc[8][4];
#pragma unroll
    for (int r = 0; r < 8; r++)
#pragma unroll
        for (int c = 0; c < 4; c++) acc[r][c] = make_float2(0.f, 0.f);

    const int nIter = K >> 3;

    float4 av = *reinterpret_cast<const float4*>(arow + akh * 4);
    float4 wv = *reinterpret_cast<const float4*>(wptr);
    As[0][akh * 4 + 0][arow_l] = av.x;
    As[0][akh * 4 + 1][arow_l] = av.y;
    As[0][akh * 4 + 2][arow_l] = av.z;
    As[0][akh * 4 + 3][arow_l] = av.w;
    *reinterpret_cast<float4*>(&Ws[0][wk][wn]) = wv;
    __syncthreads();

    for (int it = 0; it < nIter; it++) {
        const int cur = it & 1;
        if (it + 1 < nIter) {
            av = *reinterpret_cast<const float4*>(arow + (it + 1) * 8 + akh * 4);
            wv = *reinterpret_cast<const float4*>(wptr + (size_t)(it + 1) * 8 * ldw);
        }
#pragma unroll
        for (int k = 0; k < 8; k++) {
            float4 a0 = *reinterpret_cast<const float4*>(&As[cur][k][r0]);
            float4 a1 = *reinterpret_cast<const float4*>(&As[cur][k][r0 + 4]);
            float4 w0 = *reinterpret_cast<const float4*>(&Ws[cur][k][c0]);
            float4 w1 = *reinterpret_cast<const float4*>(&Ws[cur][k][c0 + 4]);
            float2 w[4];
            w[0] = make_float2(w0.x, w0.y);
            w[1] = make_float2(w0.z, w0.w);
            w[2] = make_float2(w1.x, w1.y);
            w[3] = make_float2(w1.z, w1.w);
            float ar[8] = {a0.x, a0.y, a0.z, a0.w, a1.x, a1.y, a1.z, a1.w};
#pragma unroll
            for (int r = 0; r < 8; r++) {
                float2 ad = make_float2(ar[r], ar[r]);
#pragma unroll
                for (int c = 0; c < 4; c++)
                    acc[r][c] = fma2(ad, w[c], acc[r][c]);
            }
        }
        if (it + 1 < nIter) {
            const int nxt = cur ^ 1;
            As[nxt][akh * 4 + 0][arow_l] = av.x;
            As[nxt][akh * 4 + 1][arow_l] = av.y;
            As[nxt][akh * 4 + 2][arow_l] = av.z;
            As[nxt][akh * 4 + 3][arow_l] = av.w;
            *reinterpret_cast<float4*>(&Ws[nxt][wk][wn]) = wv;
            __syncthreads();
        }
    }

    float bv[8];
#pragma unroll
    for (int j = 0; j < 8; j++) bv[j] = bias ? bias[bn + c0 + j] : 0.f;
#pragma unroll
    for (int r = 0; r < 8; r++) {
        int mrow = bm + r0 + r;
        if (mrow < M) {
            float4 o0, o1;
            o0.x = acc[r][0].x + bv[0];
            o0.y = acc[r][0].y + bv[1];
            o0.z = acc[r][1].x + bv[2];
            o0.w = acc[r][1].y + bv[3];
            o1.x = acc[r][2].x + bv[4];
            o1.y = acc[r][2].y + bv[5];
            o1.z = acc[r][3].x + bv[6];
            o1.w = acc[r][3].y + bv[7];
            *reinterpret_cast<float4*>(C + (size_t)mrow * N + bn + c0)     = o0;
            *reinterpret_cast<float4*>(C + (size_t)mrow * N + bn + c0 + 4) = o1;
        }
    }
}

// ---------------------------------------------------------------------------
// tf32 tensor-core GEMM v2 (mma.sync m16n8k8) — steps 2, 4, 6.
// ---------------------------------------------------------------------------
#define A_REG 392
#define B_REG 648
#define TF_A_WORDS (8 * A_REG)
#define TF_STAGE (TF_A_WORDS + 4 * B_REG)

__global__ __launch_bounds__(256) void gemm_tf32(
    const float* __restrict__ A,
    const float* __restrict__ emb, const int* __restrict__ idx,
    int idxTT, int idxStride, int lda,
    const float* __restrict__ W, int ldw,
    const float* __restrict__ bias,
    float* __restrict__ C, int M, int N, int K)
{
    __shared__ __align__(16) uint32_t S[2 * TF_STAGE];

    const int tid  = threadIdx.x;
    const int lane = tid & 31;
    const int wid  = tid >> 5;
    const int wm   = wid & 3;
    const int wn   = wid >> 2;
    const int g    = lane >> 2;
    const int qt   = lane & 3;

    const int bm = blockIdx.y * 128;
    const int bn = blockIdx.x * 128;

    const int arow_l = tid & 127;
    const int akh    = tid >> 7;
    int mload = bm + arow_l;
    if (mload >= M) mload = M - 1;
    const float* arow;
    if (emb) {
        int r = idx[(mload / idxTT) * idxStride + (mload % idxTT)];
        arow = emb + (size_t)r * lda;
    } else {
        arow = A + (size_t)mload * lda;
    }
    const int l_wm = arow_l >> 5;
    const int l_mr = arow_l & 31;
    const int l_g  = l_mr & 7;
    const int l_hb = (l_mr >> 3) & 1;
    const int l_mf = (l_mr >> 4) & 1;
    const int aBase = (akh * 4 + l_wm) * A_REG;

    const int wk  = tid >> 5;
    const int wn4 = (tid & 31) * 4;
    const float* wptr = W + (size_t)wk * ldw + bn + wn4;
    const int b_qt = wk & 3, b_ks = wk >> 2;
    const int b_wn = wn4 >> 6;
    const int b_nf = (wn4 & 63) >> 3;
    const int b_g0 = wn4 & 7;

    float acc[2][8][4];
#pragma unroll
    for (int mf = 0; mf < 2; mf++)
#pragma unroll
        for (int nf = 0; nf < 8; nf++)
#pragma unroll
            for (int q = 0; q < 4; q++) acc[mf][nf][q] = 0.f;

    const int nIter = K >> 4;

    float4 av0 = *reinterpret_cast<const float4*>(arow + akh * 8);
    float4 av1 = *reinterpret_cast<const float4*>(arow + akh * 8 + 4);
    float4 wv0 = *reinterpret_cast<const float4*>(wptr);
    float4 wv1 = *reinterpret_cast<const float4*>(wptr + (size_t)8 * ldw);

    {
        float a8[8] = {av0.x, av0.y, av0.z, av0.w, av1.x, av1.y, av1.z, av1.w};
#pragma unroll
        for (int j = 0; j < 8; j++) {
            int jq = j & 3, jk = j >> 2;
            S[aBase + (l_g * 4 + jq) * 12 + l_mf * 4 + jk * 2 + l_hb] = f2tf32(a8[j]);
        }
        float b8[8] = {wv0.x, wv0.y, wv0.z, wv0.w, wv1.x, wv1.y, wv1.z, wv1.w};
#pragma unroll
        for (int kk = 0; kk < 2; kk++)
#pragma unroll
            for (int cc = 0; cc < 4; cc++)
                S[TF_A_WORDS + (kk * 2 + b_wn) * B_REG +
                  ((b_g0 + cc) * 4 + b_qt) * 20 + b_nf * 2 + b_ks] =
                    f2tf32(b8[kk * 4 + cc]);
    }
    __syncthreads();

    for (int it = 0; it < nIter; it++) {
        const int off = (it & 1) ? TF_STAGE : 0;
        if (it + 1 < nIter) {
            av0 = *reinterpret_cast<const float4*>(arow + (it + 1) * 16 + akh * 8);
            av1 = *reinterpret_cast<const float4*>(arow + (it + 1) * 16 + akh * 8 + 4);
            wv0 = *reinterpret_cast<const float4*>(wptr + (size_t)(it + 1) * 16 * ldw);
            wv1 = *reinterpret_cast<const float4*>(wptr + (size_t)((it + 1) * 16 + 8) * ldw);
        }
#pragma unroll
        for (int k8 = 0; k8 < 2; k8++) {
            const uint32_t* Ab = &S[off + (k8 * 4 + wm) * A_REG + lane * 12];
            uint4 aA = *reinterpret_cast<const uint4*>(Ab);
            uint4 aB = *reinterpret_cast<const uint4*>(Ab + 4);
            const uint32_t* Bb = &S[off + TF_A_WORDS + (k8 * 2 + wn) * B_REG + lane * 20];
            uint4 q0 = *reinterpret_cast<const uint4*>(Bb);
            uint4 q1 = *reinterpret_cast<const uint4*>(Bb + 4);
            uint4 q2 = *reinterpret_cast<const uint4*>(Bb + 8);
            uint4 q3 = *reinterpret_cast<const uint4*>(Bb + 12);
            mma4(acc[0][0], aA, q0.x, q0.y); mma4(acc[1][0], aB, q0.x, q0.y);
            mma4(acc[0][1], aA, q0.z, q0.w); mma4(acc[1][1], aB, q0.z, q0.w);
            mma4(acc[0][2], aA, q1.x, q1.y); mma4(acc[1][2], aB, q1.x, q1.y);
            mma4(acc[0][3], aA, q1.z, q1.w); mma4(acc[1][3], aB, q1.z, q1.w);
            mma4(acc[0][4], aA, q2.x, q2.y); mma4(acc[1][4], aB, q2.x, q2.y);
            mma4(acc[0][5], aA, q2.z, q2.w); mma4(acc[1][5], aB, q2.z, q2.w);
            mma4(acc[0][6], aA, q3.x, q3.y); mma4(acc[1][6], aB, q3.x, q3.y);
            mma4(acc[0][7], aA, q3.z, q3.w); mma4(acc[1][7], aB, q3.z, q3.w);
        }
        if (it + 1 < nIter) {
            const int noff = (it & 1) ? 0 : TF_STAGE;
            float a8[8] = {av0.x, av0.y, av0.z, av0.w, av1.x, av1.y, av1.z, av1.w};
#pragma unroll
            for (int j = 0; j < 8; j++) {
                int jq = j & 3, jk = j >> 2;
                S[noff + aBase + (l_g * 4 + jq) * 12 + l_mf * 4 + jk * 2 + l_hb] =
                    f2tf32(a8[j]);
            }
            float b8[8] = {wv0.x, wv0.y, wv0.z, wv0.w, wv1.x, wv1.y, wv1.z, wv1.w};
#pragma unroll
            for (int kk = 0; kk < 2; kk++)
#pragma unroll
                for (int cc = 0; cc < 4; cc++)
                    S[noff + TF_A_WORDS + (kk * 2 + b_wn) * B_REG +
                      ((b_g0 + cc) * 4 + b_qt) * 20 + b_nf * 2 + b_ks] =
                        f2tf32(b8[kk * 4 + cc]);
            __syncthreads();
        }
    }

#pragma unroll
    for (int nf = 0; nf < 8; nf++) {
        int colb = bn + wn * 64 + nf * 8 + qt * 2;
        float b0 = bias ? bias[colb]     : 0.f;
        float b1 = bias ? bias[colb + 1] : 0.f;
#pragma unroll
        for (int mf = 0; mf < 2; mf++) {
            int row0 = bm + wm * 32 + mf * 16 + g;
            if (row0 < M) {
                float2 v = make_float2(acc[mf][nf][0] + b0, acc[mf][nf][1] + b1);
                *reinterpret_cast<float2*>(C + (size_t)row0 * N + colb) = v;
            }
            int row1 = row0 + 8;
            if (row1 < M) {
                float2 v = make_float2(acc[mf][nf][2] + b0, acc[mf][nf][3] + b1);
                *reinterpret_cast<float2*>(C + (size_t)row1 * N + colb) = v;
            }
        }
    }
}

// ---------------------------------------------------------------------------
// Persistent encoder v7: tensor-core (Dekker-split tf32) + SOFTWARE-PIPELINED
// HALF-BATCH BARRIERS. The batch dim is independent, so each step is split
// into halves B0 (b 0-31) and B1 (b 32-63) with separate grid barriers.
// While a block computes half B1 of step t, other blocks' B0 arrivals
// complete -> every barrier's release latency + straggler spread is hidden
// behind the other half's compute. Wh slice (96KB f32) cached in smem once
// (kills 12MB/step of repeated W reads from L2).
// ---------------------------------------------------------------------------
#define ENC_BLOCKS 128
#define ENC_THREADS 256
#define EWARPS 8
#define WSH_FLOATS (1024 * 24)            /* 96KB Wh slice (f32) */
#define ACH7 512                          /* chunk buf: hi 256 + lo 256 */
#define STG_WORDS (EWARPS * 2 * ACH7)     /* 8192 */
#define GHP_ST 26
#define GHP_WORDS (EWARPS * 32 * GHP_ST)  /* 6656 */
#define ENC_SMEM_BYTES ((WSH_FLOATS + STG_WORDS + GHP_WORDS) * 4)

#define ELOADH7(pf, cidx)                                                     \
    _Pragma("unroll")                                                         \
    for (int it = 0; it < 4; it++)                                            \
        pf[it] = *reinterpret_cast<const float2*>(                            \
            hb2 + (size_t)(it * 8 + g) * (SS * UU) + (cidx) * 8);

#define ESTAGE7(bp, pf)                                                       \
    _Pragma("unroll")                                                         \
    for (int it = 0; it < 4; it++) {                                          \
        uint32_t h0 = f2tf32(pf[it].x);                                       \
        uint32_t l0 = f2tf32(pf[it].x - __uint_as_float(h0));                 \
        uint32_t h1 = f2tf32(pf[it].y);                                       \
        uint32_t l1 = f2tf32(pf[it].y - __uint_as_float(h1));                 \
        int wi = (it >> 1) * 128 + (it & 1) + sbase;                          \
        bp[wi] = h0; bp[wi + 4] = h1;                                         \
        bp[256 + wi] = l0; bp[256 + wi + 4] = l1;                             \
    }

#define ELOADB7(wb, cidx)                                                     \
    {                                                                         \
        const float* wp_ = WshK + (cidx) * 8 * 24;                            \
        wb[0] = wp_[0];       wb[1] = wp_[4 * 24];                            \
        wb[2] = wp_[8];       wb[3] = wp_[4 * 24 + 8];                        \
        wb[4] = wp_[16];      wb[5] = wp_[4 * 24 + 16];                       \
    }

#define ECONSUME7(bp, wb)                                                     \
    {                                                                         \
        uint4 aH[2], aL[2];                                                   \
        _Pragma("unroll")                                                     \
        for (int mt = 0; mt < 2; mt++) {                                      \
            aH[mt] = *reinterpret_cast<const uint4*>(bp + mt * 128 + lane * 4);\
            aL[mt] = *reinterpret_cast<const uint4*>(bp + 256 + mt * 128 + lane * 4);\
        }                                                                     \
        _Pragma("unroll")                                                     \
        for (int nf = 0; nf < 3; nf++) {                                      \
            uint32_t p0h = f2tf32(wb[2 * nf]);                                \
            uint32_t p0l = f2tf32(wb[2 * nf] - __uint_as_float(p0h));         \
            uint32_t p1h = f2tf32(wb[2 * nf + 1]);                            \
            uint32_t p1l = f2tf32(wb[2 * nf + 1] - __uint_as_float(p1h));     \
            _Pragma("unroll")                                                 \
            for (int mt = 0; mt < 2; mt++) {                                  \
                mma4(acc[mt][nf], aH[mt], p0h, p1h);                          \
                mma4(acc[mt][nf], aH[mt], p0l, p1l);                          \
                mma4(acc[mt][nf], aL[mt], p0h, p1h);                          \
            }                                                                 \
        }                                                                     \
    }

// compute gh for one half-batch into ghp
#define ECOMPUTE_HALF(half, t)                                                \
    {                                                                         \
        float acc[2][3][4];                                                   \
        _Pragma("unroll")                                                     \
        for (int mt = 0; mt < 2; mt++)                                        \
            _Pragma("unroll")                                                 \
            for (int nf = 0; nf < 3; nf++)                                    \
                _Pragma("unroll")                                             \
                for (int q = 0; q < 4; q++) acc[mt][nf][q] = 0.f;             \
        const float* hb2 = enc_out + (size_t)((t) - 1) * UU +                 \
                           (size_t)((half) * 32) * (SS * UU) + w * 128 + kofs;\
        float2 pf0[4], pf1[4];                                                \
        float wb0[6], wb1[6];                                                 \
        ELOADH7(pf0, 0); ELOADB7(wb0, 0);                                     \
        ELOADH7(pf1, 1); ELOADB7(wb1, 1);                                     \
        ESTAGE7(buf0, pf0);                                                   \
        __syncwarp();                                                         \
        for (int cp = 0; cp < 8; cp++) {                                      \
            const int c0 = 2 * cp;                                            \
            if (c0 + 2 < 16) ELOADH7(pf0, c0 + 2);                            \
            ECONSUME7(buf0, wb0);                                             \
            if (c0 + 2 < 16) ELOADB7(wb0, c0 + 2);                            \
            ESTAGE7(buf1, pf1);                                               \
            __syncwarp();                                                     \
            if (c0 + 3 < 16) ELOADH7(pf1, c0 + 3);                            \
            ECONSUME7(buf1, wb1);                                             \
            if (c0 + 3 < 16) ELOADB7(wb1, c0 + 3);                            \
            if (c0 + 2 < 16) { ESTAGE7(buf0, pf0); __syncwarp(); }            \
        }                                                                     \
        _Pragma("unroll")                                                     \
        for (int mt = 0; mt < 2; mt++)                                        \
            _Pragma("unroll")                                                 \
            for (int nf = 0; nf < 3; nf++) {                                  \
                int r0 = mt * 16 + g;                                         \
                float* dst = ghpW + r0 * GHP_ST + nf * 8 + qt * 2;            \
                *reinterpret_cast<float2*>(dst) =                             \
                    make_float2(acc[mt][nf][0], acc[mt][nf][1]);              \
                *reinterpret_cast<float2*>(dst + 8 * GHP_ST) =                \
                    make_float2(acc[mt][nf][2], acc[mt][nf][3]);              \
            }                                                                 \
    }

// GRU epilogue for one half-batch (one (b,u) output per thread)
#define EEPILOGUE_HALF(half, t, has_gh)                                       \
    {                                                                         \
        int b  = tid >> 3;                                                    \
        int gb = (half) * 32 + b;                                             \
        float ghz = 0.f, ghr = 0.f, ghc = 0.f, hold = 0.f;                    \
        if (has_gh) {                                                         \
            _Pragma("unroll")                                                 \
            for (int w2 = 0; w2 < EWARPS; w2++) {                             \
                const float* gg = ghp + w2 * (32 * GHP_ST) + b * GHP_ST;      \
                ghz += gg[edu];                                               \
                ghr += gg[8 + edu];                                           \
                ghc += gg[16 + edu];                                          \
            }                                                                 \
            hold = enc_out[(size_t)(gb * SS + (t) - 1) * UU + eu];            \
        }                                                                     \
        const float* gxrow = gxe + (size_t)(gb * SS + (t)) * G3;              \
        float z = sigmoidf_(gxrow[eu] + ghz + b1z);                           \
        float r = sigmoidf_(gxrow[UU + eu] + ghr + b1r);                      \
        float cc = tanhf(gxrow[2 * UU + eu] + r * (ghc + b1c));               \
        enc_out[(size_t)(gb * SS + (t)) * UU + eu] = z * hold + (1.f - z) * cc;\
    }

#define EARRIVE_BAR(idx)                                                      \
    __syncthreads();                                                          \
    if (tid == 0) {                                                           \
        __threadfence();                                                      \
        unsigned old = atomicAdd(&bar[2 * (idx)], 1u);                        \
        if (old == ENC_BLOCKS - 1) {                                          \
            atomicExch(&bar[2 * (idx)], 0u);                                  \
            atomicAdd(&bar[2 * (idx) + 1], 1u);                               \
        }                                                                     \
    }

#define EWAIT_BAR(idx, tt)                                                    \
    if (tid == 0) {                                                           \
        while (*(volatile unsigned*)&bar[2 * (idx) + 1] - relbase[idx] <      \
               (unsigned)(tt)) {}                                             \
        __threadfence();                                                      \
    }                                                                         \
    __syncthreads();

__global__ __launch_bounds__(ENC_THREADS, 1) void enc_persistent(
    const float* __restrict__ gxe,   // [B*S][3U]  (includes b0)
    const float* __restrict__ Wh,    // [U][3U]
    const float* __restrict__ b1,    // [3U]
    float* __restrict__ enc_out,     // [B*S][U]
    unsigned* bar)                   // [cnt0, rel0, cnt1, rel1]
{
    extern __shared__ float sm[];
    float* Wsh = sm;                                          // [1024][24]
    uint32_t* stg = reinterpret_cast<uint32_t*>(sm + WSH_FLOATS);
    float* ghp = sm + WSH_FLOATS + STG_WORDS;                 // [8][32][26]

    const int tid  = threadIdx.x;
    const int w    = tid >> 5;
    const int lane = tid & 31;
    const int g    = lane >> 2;
    const int qt   = lane & 3;
    const int bi   = blockIdx.x;
    const int u0   = bi * 8;

    const int lqh  = lane & 1;
    const int lkh  = (lane >> 1) & 1;
    const int kofs = lkh * 4 + lqh * 2;
    const int sbase = g * 16 + lqh * 8 + lkh * 2;

    uint32_t* buf0 = stg + w * 2 * ACH7;
    uint32_t* buf1 = buf0 + ACH7;
    float* ghpW = ghp + w * 32 * GHP_ST;

    // Wh slice into smem: Wsh[k][gate*8+du] = Wh[k][gate*1024 + u0 + du]
    for (int i = tid; i < WSH_FLOATS; i += ENC_THREADS) {
        int k = i / 24, c = i % 24;
        Wsh[i] = Wh[(size_t)k * G3 + (c >> 3) * UU + u0 + (c & 7)];
    }
    // per-lane W base: k = w*128 + qt, col group g
    const float* WshK = Wsh + (w * 128 + qt) * 24 + g;

    __shared__ unsigned relbase_s[2];
    if (tid == 0) {
        relbase_s[0] = *(volatile unsigned*)&bar[1];
        relbase_s[1] = *(volatile unsigned*)&bar[3];
    }
    __syncthreads();
    const unsigned relbase[2] = {relbase_s[0], relbase_s[1]};

    const int edu = tid & 7;
    const int eu  = u0 + edu;
    const float b1z = b1[eu], b1r = b1[UU + eu], b1c = b1[2 * UU + eu];

    // ---- t = 0: gx-only for both halves ----
    EEPILOGUE_HALF(0, 0, false);
    EARRIVE_BAR(0);
    EEPILOGUE_HALF(1, 0, false);
    EARRIVE_BAR(1);

    for (int t = 1; t < SS; t++) {
        EWAIT_BAR(0, t);          // release happened during our B1(t-1) work
        ECOMPUTE_HALF(0, t);
        __syncthreads();
        EEPILOGUE_HALF(0, t, true);
        EARRIVE_BAR(0);
        EWAIT_BAR(1, t);
        ECOMPUTE_HALF(1, t);
        __syncthreads();
        EEPILOGUE_HALF(1, t, true);
        EARRIVE_BAR(1);
    }
}

// ---------------------------------------------------------------------------
// Persistent decoder: ONE launch, 64 blocks (one per batch), all 39 steps.
// ---------------------------------------------------------------------------
#define DEC_SMEM_FLOATS (SS * UU + G3 + UU + 64)
#define DEC_SMEM_BYTES (DEC_SMEM_FLOATS * 4)

__global__ __launch_bounds__(256, 1) void dec_persistent(
    const float* __restrict__ enc_out,
    const float* __restrict__ P,
    const float* __restrict__ gxd,
    const float* __restrict__ db1,
    float* __restrict__ hdec)
{
    extern __shared__ float dsm[];
    float* enc_sh = dsm;
    float* gxc    = dsm + SS * UU;
    float* h_sh   = gxc + G3;
    float* wsm    = h_sh + UU;

    const int b   = blockIdx.x;
    const int tid = threadIdx.x;
    const int warp = tid >> 5, lane = tid & 31;

    {
        const float4* src = reinterpret_cast<const float4*>(enc_out + (size_t)b * SS * UU);
        float4* dst = reinterpret_cast<float4*>(enc_sh);
        for (int i = tid; i < SS * UU / 4; i += 256) dst[i] = src[i];
    }
    __syncthreads();
    for (int i = tid; i < UU; i += 256) h_sh[i] = enc_sh[(SS - 1) * UU + i];
    __syncthreads();

    const float* Pb = P + (size_t)b * SS * G3;

    for (int t = 0; t < TD; t++) {
        {
            float acc[5] = {0.f, 0.f, 0.f, 0.f, 0.f};
#pragma unroll 4
            for (int i = 0; i < 32; i++) {
                int uidx = lane + 32 * i;
                float hv = h_sh[uidx];
#pragma unroll
                for (int q = 0; q < 5; q++)
                    acc[q] += hv * enc_sh[(warp * 5 + q) * UU + uidx];
            }
#pragma unroll
            for (int q = 0; q < 5; q++) {
                float v = acc[q];
                for (int o = 16; o; o >>= 1) v += __shfl_xor_sync(0xffffffffu, v, o);
                if (lane == 0) wsm[warp * 5 + q] = v;
            }
        }
        __syncthreads();

        if (tid == 0) {
            float mx = -1e30f;
            for (int s = 0; s < SS; s++) mx = fmaxf(mx, wsm[s]);
            float smv = 0.f;
            for (int s = 0; s < SS; s++) { float e = expf(wsm[s] - mx); wsm[s] = e; smv += e; }
            float inv = 1.f / smv;
            for (int s = 0; s < SS; s++) wsm[s] *= inv;
        }
        __syncthreads();

        {
            float a[12];
#pragma unroll
            for (int i = 0; i < 12; i++) a[i] = 0.f;
            for (int s = 0; s < SS; s++) {
                float w = wsm[s];
                const float* row = Pb + (size_t)s * G3;
#pragma unroll
                for (int i = 0; i < 12; i++)
                    a[i] += w * row[tid + i * 256];
            }
#pragma unroll
            for (int i = 0; i < 12; i++) gxc[tid + i * 256] = a[i];
        }
        __syncthreads();

        {
            const float* gx = gxd + (size_t)(b * TD + t) * G3;
            float* ho = hdec + (size_t)(b * TD + t) * UU;
#pragma unroll
            for (int i = 0; i < 4; i++) {
                int u = tid + i * 256;
                float z = sigmoidf_(gxc[u] + gx[u] + db1[u]);
                float r = sigmoidf_(gxc[UU + u] + gx[UU + u] + db1[UU + u]);
                float c = tanhf(gxc[2 * UU + u] + gx[2 * UU + u] + r * db1[2 * UU + u]);
                float hn = (1.f - z) * c;
                h_sh[u] = hn;
                ho[u] = hn;
            }
        }
        __syncthreads();
    }
}

// ---------------------------------------------------------------------------
extern "C" void kernel_launch(void* const* d_in, const int* in_sizes, int n_in,
                              void* d_out, int out_size)
{
    const int*   inp     = (const int*)d_in[0];
    const int*   targ    = (const int*)d_in[1];
    const float* enc_emb = (const float*)d_in[2];
    const float* enc_Wx  = (const float*)d_in[3];
    const float* enc_Wh  = (const float*)d_in[4];
    const float* enc_b   = (const float*)d_in[5];
    const float* dec_emb = (const float*)d_in[6];
    const float* dec_Wx  = (const float*)d_in[7];
    // d_in[8] = dec_Wh: provably unused (decoder GRU hidden input is zeros)
    const float* dec_b   = (const float*)d_in[9];
    const float* fc_W    = (const float*)d_in[10];
    const float* fc_b    = (const float*)d_in[11];
    float* out = (float*)d_out;

    float *gxe, *gxd, *enc_out, *P, *hdec;
    unsigned* bar;
    cudaGetSymbolAddress((void**)&gxe,     g_gxe);
    cudaGetSymbolAddress((void**)&gxd,     g_gxd);
    cudaGetSymbolAddress((void**)&enc_out, g_enc_out);
    cudaGetSymbolAddress((void**)&P,       g_P);
    cudaGetSymbolAddress((void**)&hdec,    g_hdec);
    cudaGetSymbolAddress((void**)&bar,     g_bar);

    cudaFuncSetAttribute(enc_persistent,
                         cudaFuncAttributeMaxDynamicSharedMemorySize, ENC_SMEM_BYTES);
    cudaFuncSetAttribute(dec_persistent,
                         cudaFuncAttributeMaxDynamicSharedMemorySize, DEC_SMEM_BYTES);

    // 1) Encoder gx (fp32 — feeds the recurrence, keep full precision)
    gemm_f32<<<dim3(G3 / 128, (BB * SS + 127) / 128), 256>>>(
        nullptr, enc_emb, inp, SS, SS, EE,
        enc_Wx, G3, enc_b, gxe, BB * SS, G3, EE);

    // 2) Decoder xt-part gx (tf32 tensor path)
    gemm_tf32<<<dim3(G3 / 128, (BB * TD + 127) / 128), 256>>>(
        nullptr, dec_emb, targ, TD, SS, EE,
        dec_Wx + (size_t)UU * G3, G3, dec_b, gxd, BB * TD, G3, EE);

    // 3) Encoder recurrence: half-batch pipelined tensor kernel
    enc_persistent<<<ENC_BLOCKS, ENC_THREADS, ENC_SMEM_BYTES>>>(
        gxe, enc_Wh, enc_b + G3, enc_out, bar);

    // 4) P = enc_out @ dec_Wx[:U]   (tf32 tensor path)
    gemm_tf32<<<dim3(G3 / 128, (BB * SS + 127) / 128), 256>>>(
        enc_out, nullptr, nullptr, 1, 1, UU,
        dec_Wx, G3, nullptr, P, BB * SS, G3, UU);

    // 5) Decoder recurrence: ONE persistent kernel (batch-parallel)
    dec_persistent<<<BB, 256, DEC_SMEM_BYTES>>>(
        enc_out, P, gxd, dec_b + G3, hdec);

    // 6) Batched output projection (tf32 tensor path)
    gemm_tf32<<<dim3(VV / 128, (BB * TD + 127) / 128), 256>>>(
        hdec, nullptr, nullptr, 1, 1, UU,
        fc_W, VV, fc_b, out, BB * TD, VV, UU);
}

// round 14
// speedup vs baseline: 1.0828x; 1.0828x over previous
#include <cuda_runtime.h>
#include <math.h>
#include <stdint.h>
#include <string.h>

#define BB 64
#define SS 40
#define TD 39
#define EE 256
#define UU 1024
#define VV 8192
#define G3 3072

// Scratch (device globals; no allocation allowed)
static __device__ float g_gxe[BB * SS * G3];      // encoder x@Wx + b0
static __device__ float g_gxd[BB * TD * G3];      // decoder xt@Wx_bot + b0
static __device__ float g_enc_out[BB * SS * UU];  // encoder hidden sequence
static __device__ float g_P[BB * SS * G3];        // enc_out @ dec_Wx[:U]
static __device__ float g_hdec[BB * TD * UU];     // decoder hidden per step
static __device__ unsigned g_bar[4];              // [cnt, rel, -, -]

// ---------------------------------------------------------------------------
__device__ __forceinline__ float2 fma2(float2 a, float2 b, float2 c) {
    unsigned long long ua, ub, uc;
    memcpy(&ua, &a, 8); memcpy(&ub, &b, 8); memcpy(&uc, &c, 8);
    asm("fma.rn.f32x2 %0, %1, %2, %0;" : "+l"(uc) : "l"(ua), "l"(ub));
    float2 r; memcpy(&r, &uc, 8);
    return r;
}

__device__ __forceinline__ float sigmoidf_(float x) {
    return 1.0f / (1.0f + expf(-x));
}

__device__ __forceinline__ uint32_t f2tf32(float x) {
    uint32_t r;
    asm("cvt.rna.tf32.f32 %0, %1;" : "=r"(r) : "f"(x));
    return r;
}

__device__ __forceinline__ void mma4(float c[4], const uint4& a,
                                     uint32_t b0, uint32_t b1) {
    asm("mma.sync.aligned.m16n8k8.row.col.f32.tf32.tf32.f32 "
        "{%0,%1,%2,%3},{%4,%5,%6,%7},{%8,%9},{%0,%1,%2,%3};"
        : "+f"(c[0]), "+f"(c[1]), "+f"(c[2]), "+f"(c[3])
        : "r"(a.x), "r"(a.y), "r"(a.z), "r"(a.w), "r"(b0), "r"(b1));
}

// ---------------------------------------------------------------------------
// fp32 GEMM (scalar f32x2 path) — step 1 only (feeds the recurrence).
// ---------------------------------------------------------------------------
__global__ __launch_bounds__(256, 2) void gemm_f32(
    const float* __restrict__ A,
    const float* __restrict__ emb, const int* __restrict__ idx,
    int idxTT, int idxStride, int lda,
    const float* __restrict__ W, int ldw,
    const float* __restrict__ bias,
    float* __restrict__ C, int M, int N, int K)
{
    __shared__ __align__(16) float As[2][8][128];
    __shared__ __align__(16) float Ws[2][8][128];

    const int tid = threadIdx.x;
    const int bm = blockIdx.y * 128;
    const int bn = blockIdx.x * 128;

    const int arow_l = tid & 127;
    const int akh    = tid >> 7;
    int mload = bm + arow_l;
    if (mload >= M) mload = M - 1;
    const float* arow;
    if (emb) {
        int r = idx[(mload / idxTT) * idxStride + (mload % idxTT)];
        arow = emb + (size_t)r * lda;
    } else {
        arow = A + (size_t)mload * lda;
    }

    const int wk = tid >> 5;
    const int wn = (tid & 31) * 4;
    const float* wptr = W + (size_t)wk * ldw + bn + wn;

    const int tx = tid & 15, ty = tid >> 4;
    const int r0 = ty * 8, c0 = tx * 8;

    float2 acc[8][4];
#pragma unroll
    for (int r = 0; r < 8; r++)
#pragma unroll
        for (int c = 0; c < 4; c++) acc[r][c] = make_float2(0.f, 0.f);

    const int nIter = K >> 3;

    float4 av = *reinterpret_cast<const float4*>(arow + akh * 4);
    float4 wv = *reinterpret_cast<const float4*>(wptr);
    As[0][akh * 4 + 0][arow_l] = av.x;
    As[0][akh * 4 + 1][arow_l] = av.y;
    As[0][akh * 4 + 2][arow_l] = av.z;
    As[0][akh * 4 + 3][arow_l] = av.w;
    *reinterpret_cast<float4*>(&Ws[0][wk][wn]) = wv;
    __syncthreads();

    for (int it = 0; it < nIter; it++) {
        const int cur = it & 1;
        if (it + 1 < nIter) {
            av = *reinterpret_cast<const float4*>(arow + (it + 1) * 8 + akh * 4);
            wv = *reinterpret_cast<const float4*>(wptr + (size_t)(it + 1) * 8 * ldw);
        }
#pragma unroll
        for (int k = 0; k < 8; k++) {
            float4 a0 = *reinterpret_cast<const float4*>(&As[cur][k][r0]);
            float4 a1 = *reinterpret_cast<const float4*>(&As[cur][k][r0 + 4]);
            float4 w0 = *reinterpret_cast<const float4*>(&Ws[cur][k][c0]);
            float4 w1 = *reinterpret_cast<const float4*>(&Ws[cur][k][c0 + 4]);
            float2 w[4];
            w[0] = make_float2(w0.x, w0.y);
            w[1] = make_float2(w0.z, w0.w);
            w[2] = make_float2(w1.x, w1.y);
            w[3] = make_float2(w1.z, w1.w);
            float ar[8] = {a0.x, a0.y, a0.z, a0.w, a1.x, a1.y, a1.z, a1.w};
#pragma unroll
            for (int r = 0; r < 8; r++) {
                float2 ad = make_float2(ar[r], ar[r]);
#pragma unroll
                for (int c = 0; c < 4; c++)
                    acc[r][c] = fma2(ad, w[c], acc[r][c]);
            }
        }
        if (it + 1 < nIter) {
            const int nxt = cur ^ 1;
            As[nxt][akh * 4 + 0][arow_l] = av.x;
            As[nxt][akh * 4 + 1][arow_l] = av.y;
            As[nxt][akh * 4 + 2][arow_l] = av.z;
            As[nxt][akh * 4 + 3][arow_l] = av.w;
            *reinterpret_cast<float4*>(&Ws[nxt][wk][wn]) = wv;
            __syncthreads();
        }
    }

    float bv[8];
#pragma unroll
    for (int j = 0; j < 8; j++) bv[j] = bias ? bias[bn + c0 + j] : 0.f;
#pragma unroll
    for (int r = 0; r < 8; r++) {
        int mrow = bm + r0 + r;
        if (mrow < M) {
            float4 o0, o1;
            o0.x = acc[r][0].x + bv[0];
            o0.y = acc[r][0].y + bv[1];
            o0.z = acc[r][1].x + bv[2];
            o0.w = acc[r][1].y + bv[3];
            o1.x = acc[r][2].x + bv[4];
            o1.y = acc[r][2].y + bv[5];
            o1.z = acc[r][3].x + bv[6];
            o1.w = acc[r][3].y + bv[7];
            *reinterpret_cast<float4*>(C + (size_t)mrow * N + bn + c0)     = o0;
            *reinterpret_cast<float4*>(C + (size_t)mrow * N + bn + c0 + 4) = o1;
        }
    }
}

// ---------------------------------------------------------------------------
// tf32 tensor-core GEMM v3 (mma.sync m16n8k8) — steps 2, 4, 6.
// 128x128 block, BK=16, 128 threads = 4 warps in 2x2, WARP TILE 64x64
// (2x the operand reuse of 32x64: 125 B/MMA vs 187 -> crossbar relief).
// smem [k][row/col] with TFS=136: scalar LDS banks (8*qt+g) conflict-free
// (R8-verified map). A staged via conflict-free scalar STS, B via
// conflict-free STS.128. Double-buffered, one syncthreads per iter.
// ---------------------------------------------------------------------------
#define TFS 136

__global__ __launch_bounds__(128, 2) void gemm_tf32(
    const float* __restrict__ A,
    const float* __restrict__ emb, const int* __restrict__ idx,
    int idxTT, int idxStride, int lda,
    const float* __restrict__ W, int ldw,
    const float* __restrict__ bias,
    float* __restrict__ C, int M, int N, int K)
{
    __shared__ __align__(16) uint32_t Ast[2][16][TFS];
    __shared__ __align__(16) uint32_t Bst[2][16][TFS];

    const int tid  = threadIdx.x;
    const int lane = tid & 31;
    const int wid  = tid >> 5;
    const int wm   = wid & 1;          // row half (64 rows)
    const int wn   = wid >> 1;         // col half (64 cols)
    const int g    = lane >> 2;
    const int qt   = lane & 3;

    const int bm = blockIdx.y * 128;
    const int bn = blockIdx.x * 128;

    // A loader: row = tid (0..127), 16 k per iter (4 float4)
    int mload = bm + tid;
    if (mload >= M) mload = M - 1;
    const float* arow;
    if (emb) {
        int r = idx[(mload / idxTT) * idxStride + (mload % idxTT)];
        arow = emb + (size_t)r * lda;
    } else {
        arow = A + (size_t)mload * lda;
    }

    // B loader: k row = tid>>3 (0..15), cols (tid&7)*4 + j*32, j=0..3
    const int bk = tid >> 3;
    const int bc = (tid & 7) * 4;
    const float* wptr = W + (size_t)bk * ldw + bn + bc;

    float acc[4][8][4];
#pragma unroll
    for (int mf = 0; mf < 4; mf++)
#pragma unroll
        for (int nf = 0; nf < 8; nf++)
#pragma unroll
            for (int q = 0; q < 4; q++) acc[mf][nf][q] = 0.f;

    const int nIter = K >> 4;

    float4 av[4], bvv[4];
#pragma unroll
    for (int j = 0; j < 4; j++) {
        av[j]  = *reinterpret_cast<const float4*>(arow + j * 4);
        bvv[j] = *reinterpret_cast<const float4*>(wptr + j * 32);
    }
    {
        const float* ap = reinterpret_cast<const float*>(av);
#pragma unroll
        for (int j = 0; j < 16; j++) Ast[0][j][tid] = f2tf32(ap[j]);
#pragma unroll
        for (int j = 0; j < 4; j++) {
            uint4 p = make_uint4(f2tf32(bvv[j].x), f2tf32(bvv[j].y),
                                 f2tf32(bvv[j].z), f2tf32(bvv[j].w));
            *reinterpret_cast<uint4*>(&Bst[0][bk][bc + j * 32]) = p;
        }
    }
    __syncthreads();

    for (int it = 0; it < nIter; it++) {
        const int cur = it & 1;
        if (it + 1 < nIter) {
#pragma unroll
            for (int j = 0; j < 4; j++) {
                av[j]  = *reinterpret_cast<const float4*>(arow + (it + 1) * 16 + j * 4);
                bvv[j] = *reinterpret_cast<const float4*>(
                    wptr + (size_t)(it + 1) * 16 * ldw + j * 32);
            }
        }
#pragma unroll
        for (int k8 = 0; k8 < 2; k8++) {
            uint4 afrag[4];
#pragma unroll
            for (int mf = 0; mf < 4; mf++) {
                int R = wm * 64 + mf * 16;
                afrag[mf].x = Ast[cur][k8 * 8 + qt][R + g];
                afrag[mf].y = Ast[cur][k8 * 8 + qt][R + g + 8];
                afrag[mf].z = Ast[cur][k8 * 8 + qt + 4][R + g];
                afrag[mf].w = Ast[cur][k8 * 8 + qt + 4][R + g + 8];
            }
#pragma unroll
            for (int nf = 0; nf < 8; nf++) {
                int cidx = wn * 64 + nf * 8 + g;
                uint32_t b0 = Bst[cur][k8 * 8 + qt][cidx];
                uint32_t b1 = Bst[cur][k8 * 8 + qt + 4][cidx];
#pragma unroll
                for (int mf = 0; mf < 4; mf++)
                    mma4(acc[mf][nf], afrag[mf], b0, b1);
            }
        }
        if (it + 1 < nIter) {
            const int nxt = cur ^ 1;
            const float* ap = reinterpret_cast<const float*>(av);
#pragma unroll
            for (int j = 0; j < 16; j++) Ast[nxt][j][tid] = f2tf32(ap[j]);
#pragma unroll
            for (int j = 0; j < 4; j++) {
                uint4 p = make_uint4(f2tf32(bvv[j].x), f2tf32(bvv[j].y),
                                     f2tf32(bvv[j].z), f2tf32(bvv[j].w));
                *reinterpret_cast<uint4*>(&Bst[nxt][bk][bc + j * 32]) = p;
            }
            __syncthreads();
        }
    }

    // Epilogue: c0,c1 -> (row g, cols qt*2, qt*2+1); c2,c3 -> row g+8
#pragma unroll
    for (int nf = 0; nf < 8; nf++) {
        int colb = bn + wn * 64 + nf * 8 + qt * 2;
        float b0 = bias ? bias[colb]     : 0.f;
        float b1 = bias ? bias[colb + 1] : 0.f;
#pragma unroll
        for (int mf = 0; mf < 4; mf++) {
            int row0 = bm + wm * 64 + mf * 16 + g;
            if (row0 < M) {
                float2 v = make_float2(acc[mf][nf][0] + b0, acc[mf][nf][1] + b1);
                *reinterpret_cast<float2*>(C + (size_t)row0 * N + colb) = v;
            }
            int row1 = row0 + 8;
            if (row1 < M) {
                float2 v = make_float2(acc[mf][nf][2] + b0, acc[mf][nf][3] + b1);
                *reinterpret_cast<float2*>(C + (size_t)row1 * N + colb) = v;
            }
        }
    }
}

// ---------------------------------------------------------------------------
// Persistent encoder recurrence v6 (R12 version — best measured): tensor-core
// Dekker-split tf32, 128 blocks x 256 threads, 8 warp k-splits, single
// grid barrier per step with leader-only fences.
// ---------------------------------------------------------------------------
#define ENC_BLOCKS 128
#define ENC_THREADS 256
#define EWARPS 8
#define ACH 1024
#define ENC_STG_WORDS (EWARPS * 2 * ACH)
#define GHP_ST 26
#define GHP_WORDS (EWARPS * 64 * GHP_ST)
#define ENC_SMEM_BYTES ((ENC_STG_WORDS + GHP_WORDS) * 4)

#define ELOADH(pf, cidx)                                                      \
    _Pragma("unroll")                                                         \
    for (int it = 0; it < 8; it++)                                            \
        pf[it] = *reinterpret_cast<const float2*>(                            \
            hb2 + (size_t)(it * 8 + g) * (SS * UU) + (cidx) * 8);

#define ESTAGE(bp, pf)                                                        \
    _Pragma("unroll")                                                         \
    for (int it = 0; it < 8; it++) {                                          \
        uint32_t h0 = f2tf32(pf[it].x);                                       \
        uint32_t l0 = f2tf32(pf[it].x - __uint_as_float(h0));                 \
        uint32_t h1 = f2tf32(pf[it].y);                                       \
        uint32_t l1 = f2tf32(pf[it].y - __uint_as_float(h1));                 \
        int wi = (it >> 1) * 128 + (it & 1) + sbase;                          \
        bp[wi] = h0; bp[wi + 4] = h1;                                         \
        bp[512 + wi] = l0; bp[512 + wi + 4] = l1;                             \
    }

#define ELOADB(wb, cidx)                                                      \
    {                                                                         \
        const float* wp_ = wB + (size_t)(cidx) * (8 * G3);                    \
        wb[0] = wp_[0];      wb[1] = wp_[4 * G3];                             \
        wb[2] = wp_[UU];     wb[3] = wp_[UU + 4 * G3];                        \
        wb[4] = wp_[2 * UU]; wb[5] = wp_[2 * UU + 4 * G3];                    \
    }

#define ECONSUME(bp, wb)                                                      \
    {                                                                         \
        uint4 aH[4], aL[4];                                                   \
        _Pragma("unroll")                                                     \
        for (int mt = 0; mt < 4; mt++) {                                      \
            aH[mt] = *reinterpret_cast<const uint4*>(bp + mt * 128 + lane * 4);\
            aL[mt] = *reinterpret_cast<const uint4*>(bp + 512 + mt * 128 + lane * 4);\
        }                                                                     \
        _Pragma("unroll")                                                     \
        for (int nf = 0; nf < 3; nf++) {                                      \
            uint32_t p0h = f2tf32(wb[2 * nf]);                                \
            uint32_t p0l = f2tf32(wb[2 * nf] - __uint_as_float(p0h));         \
            uint32_t p1h = f2tf32(wb[2 * nf + 1]);                            \
            uint32_t p1l = f2tf32(wb[2 * nf + 1] - __uint_as_float(p1h));     \
            _Pragma("unroll")                                                 \
            for (int mt = 0; mt < 4; mt++) {                                  \
                mma4(acc[mt][nf], aH[mt], p0h, p1h);                          \
                mma4(acc[mt][nf], aH[mt], p0l, p1l);                          \
                mma4(acc[mt][nf], aL[mt], p0h, p1h);                          \
            }                                                                 \
        }                                                                     \
    }

__global__ __launch_bounds__(ENC_THREADS, 1) void enc_persistent(
    const float* __restrict__ gxe,   // [B*S][3U]  (includes b0)
    const float* __restrict__ Wh,    // [U][3U]
    const float* __restrict__ b1,    // [3U]
    float* __restrict__ enc_out,     // [B*S][U]
    unsigned* bar_cnt, unsigned* bar_rel)
{
    extern __shared__ float sm[];
    uint32_t* stg = reinterpret_cast<uint32_t*>(sm);   // [8 warps][2][1024]
    float* ghp = sm + ENC_STG_WORDS;                   // [8 warps][64][26]

    const int tid  = threadIdx.x;
    const int w    = tid >> 5;
    const int lane = tid & 31;
    const int g    = lane >> 2;
    const int qt   = lane & 3;
    const int bi   = blockIdx.x;
    const int u0   = bi * 8;

    const int lqh  = lane & 1;
    const int lkh  = (lane >> 1) & 1;
    const int kofs = lkh * 4 + lqh * 2;
    const int sbase = g * 16 + lqh * 8 + lkh * 2;

    uint32_t* buf0 = stg + w * 2 * ACH;
    uint32_t* buf1 = buf0 + ACH;
    float* ghpW = ghp + w * 64 * GHP_ST;

    const float* wB = Wh + (size_t)(w * 128 + qt) * G3 + u0 + g;

    __shared__ unsigned relbase_s;
    if (tid == 0) relbase_s = *(volatile unsigned*)bar_rel;
    __syncthreads();
    const unsigned relbase = relbase_s;

    const int edu = tid & 7;
    const int eu  = u0 + edu;
    const float b1z = b1[eu], b1r = b1[UU + eu], b1c = b1[2 * UU + eu];

    for (int t = 0; t < SS; t++) {
        if (t > 0) {
            __syncthreads();
            if (tid == 0) {
                __threadfence();
                unsigned old = atomicAdd(bar_cnt, 1u);
                if (old == ENC_BLOCKS - 1) {
                    atomicExch(bar_cnt, 0u);
                    atomicAdd(bar_rel, 1u);
                }
                while (*(volatile unsigned*)bar_rel - relbase < (unsigned)t) {}
                __threadfence();
            }
            __syncthreads();

            float acc[4][3][4];
#pragma unroll
            for (int mt = 0; mt < 4; mt++)
#pragma unroll
                for (int nf = 0; nf < 3; nf++)
#pragma unroll
                    for (int q = 0; q < 4; q++) acc[mt][nf][q] = 0.f;

            const float* hb2 = enc_out + (size_t)(t - 1) * UU + w * 128 + kofs;

            float2 pf0[8], pf1[8];
            float wb0[6], wb1[6];

            ELOADH(pf0, 0); ELOADB(wb0, 0);
            ELOADH(pf1, 1); ELOADB(wb1, 1);
            ESTAGE(buf0, pf0);
            __syncwarp();

            for (int cp = 0; cp < 8; cp++) {
                const int c0 = 2 * cp;
                if (c0 + 2 < 16) ELOADH(pf0, c0 + 2);
                ECONSUME(buf0, wb0);
                if (c0 + 2 < 16) ELOADB(wb0, c0 + 2);
                ESTAGE(buf1, pf1);
                __syncwarp();
                if (c0 + 3 < 16) ELOADH(pf1, c0 + 3);
                ECONSUME(buf1, wb1);
                if (c0 + 3 < 16) ELOADB(wb1, c0 + 3);
                if (c0 + 2 < 16) {
                    ESTAGE(buf0, pf0);
                    __syncwarp();
                }
            }

#pragma unroll
            for (int mt = 0; mt < 4; mt++)
#pragma unroll
                for (int nf = 0; nf < 3; nf++) {
                    int r0 = mt * 16 + g;
                    float* dst = ghpW + r0 * GHP_ST + nf * 8 + qt * 2;
                    *reinterpret_cast<float2*>(dst) =
                        make_float2(acc[mt][nf][0], acc[mt][nf][1]);
                    *reinterpret_cast<float2*>(dst + 8 * GHP_ST) =
                        make_float2(acc[mt][nf][2], acc[mt][nf][3]);
                }
        }
        __syncthreads();

#pragma unroll
        for (int i = 0; i < 2; i++) {
            int b = (tid >> 3) + i * 32;
            float ghz = 0.f, ghr = 0.f, ghc = 0.f, hold = 0.f;
            if (t > 0) {
#pragma unroll
                for (int w2 = 0; w2 < EWARPS; w2++) {
                    const float* gg = ghp + w2 * (64 * GHP_ST) + b * GHP_ST;
                    ghz += gg[edu];
                    ghr += gg[8 + edu];
                    ghc += gg[16 + edu];
                }
                hold = enc_out[(size_t)(b * SS + t - 1) * UU + eu];
            }
            const float* gxrow = gxe + (size_t)(b * SS + t) * G3;
            float z = sigmoidf_(gxrow[eu] + ghz + b1z);
            float r = sigmoidf_(gxrow[UU + eu] + ghr + b1r);
            float cc = tanhf(gxrow[2 * UU + eu] + r * (ghc + b1c));
            enc_out[(size_t)(b * SS + t) * UU + eu] = z * hold + (1.f - z) * cc;
        }
    }
}

// ---------------------------------------------------------------------------
// Persistent decoder: ONE launch, 64 blocks (one per batch), all 39 steps.
// ---------------------------------------------------------------------------
#define DEC_SMEM_FLOATS (SS * UU + G3 + UU + 64)
#define DEC_SMEM_BYTES (DEC_SMEM_FLOATS * 4)

__global__ __launch_bounds__(256, 1) void dec_persistent(
    const float* __restrict__ enc_out,
    const float* __restrict__ P,
    const float* __restrict__ gxd,
    const float* __restrict__ db1,
    float* __restrict__ hdec)
{
    extern __shared__ float dsm[];
    float* enc_sh = dsm;
    float* gxc    = dsm + SS * UU;
    float* h_sh   = gxc + G3;
    float* wsm    = h_sh + UU;

    const int b   = blockIdx.x;
    const int tid = threadIdx.x;
    const int warp = tid >> 5, lane = tid & 31;

    {
        const float4* src = reinterpret_cast<const float4*>(enc_out + (size_t)b * SS * UU);
        float4* dst = reinterpret_cast<float4*>(enc_sh);
        for (int i = tid; i < SS * UU / 4; i += 256) dst[i] = src[i];
    }
    __syncthreads();
    for (int i = tid; i < UU; i += 256) h_sh[i] = enc_sh[(SS - 1) * UU + i];
    __syncthreads();

    const float* Pb = P + (size_t)b * SS * G3;

    for (int t = 0; t < TD; t++) {
        {
            float acc[5] = {0.f, 0.f, 0.f, 0.f, 0.f};
#pragma unroll 4
            for (int i = 0; i < 32; i++) {
                int uidx = lane + 32 * i;
                float hv = h_sh[uidx];
#pragma unroll
                for (int q = 0; q < 5; q++)
                    acc[q] += hv * enc_sh[(warp * 5 + q) * UU + uidx];
            }
#pragma unroll
            for (int q = 0; q < 5; q++) {
                float v = acc[q];
                for (int o = 16; o; o >>= 1) v += __shfl_xor_sync(0xffffffffu, v, o);
                if (lane == 0) wsm[warp * 5 + q] = v;
            }
        }
        __syncthreads();

        if (tid == 0) {
            float mx = -1e30f;
            for (int s = 0; s < SS; s++) mx = fmaxf(mx, wsm[s]);
            float smv = 0.f;
            for (int s = 0; s < SS; s++) { float e = expf(wsm[s] - mx); wsm[s] = e; smv += e; }
            float inv = 1.f / smv;
            for (int s = 0; s < SS; s++) wsm[s] *= inv;
        }
        __syncthreads();

        {
            float a[12];
#pragma unroll
            for (int i = 0; i < 12; i++) a[i] = 0.f;
            for (int s = 0; s < SS; s++) {
                float w = wsm[s];
                const float* row = Pb + (size_t)s * G3;
#pragma unroll
                for (int i = 0; i < 12; i++)
                    a[i] += w * row[tid + i * 256];
            }
#pragma unroll
            for (int i = 0; i < 12; i++) gxc[tid + i * 256] = a[i];
        }
        __syncthreads();

        {
            const float* gx = gxd + (size_t)(b * TD + t) * G3;
            float* ho = hdec + (size_t)(b * TD + t) * UU;
#pragma unroll
            for (int i = 0; i < 4; i++) {
                int u = tid + i * 256;
                float z = sigmoidf_(gxc[u] + gx[u] + db1[u]);
                float r = sigmoidf_(gxc[UU + u] + gx[UU + u] + db1[UU + u]);
                float c = tanhf(gxc[2 * UU + u] + gx[2 * UU + u] + r * db1[2 * UU + u]);
                float hn = (1.f - z) * c;
                h_sh[u] = hn;
                ho[u] = hn;
            }
        }
        __syncthreads();
    }
}

// ---------------------------------------------------------------------------
extern "C" void kernel_launch(void* const* d_in, const int* in_sizes, int n_in,
                              void* d_out, int out_size)
{
    const int*   inp     = (const int*)d_in[0];
    const int*   targ    = (const int*)d_in[1];
    const float* enc_emb = (const float*)d_in[2];
    const float* enc_Wx  = (const float*)d_in[3];
    const float* enc_Wh  = (const float*)d_in[4];
    const float* enc_b   = (const float*)d_in[5];
    const float* dec_emb = (const float*)d_in[6];
    const float* dec_Wx  = (const float*)d_in[7];
    // d_in[8] = dec_Wh: provably unused (decoder GRU hidden input is zeros)
    const float* dec_b   = (const float*)d_in[9];
    const float* fc_W    = (const float*)d_in[10];
    const float* fc_b    = (const float*)d_in[11];
    float* out = (float*)d_out;

    float *gxe, *gxd, *enc_out, *P, *hdec;
    unsigned* bar;
    cudaGetSymbolAddress((void**)&gxe,     g_gxe);
    cudaGetSymbolAddress((void**)&gxd,     g_gxd);
    cudaGetSymbolAddress((void**)&enc_out, g_enc_out);
    cudaGetSymbolAddress((void**)&P,       g_P);
    cudaGetSymbolAddress((void**)&hdec,    g_hdec);
    cudaGetSymbolAddress((void**)&bar,     g_bar);

    cudaFuncSetAttribute(enc_persistent,
                         cudaFuncAttributeMaxDynamicSharedMemorySize, ENC_SMEM_BYTES);
    cudaFuncSetAttribute(dec_persistent,
                         cudaFuncAttributeMaxDynamicSharedMemorySize, DEC_SMEM_BYTES);

    // 1) Encoder gx (fp32 — feeds the recurrence, keep full precision)
    gemm_f32<<<dim3(G3 / 128, (BB * SS + 127) / 128), 256>>>(
        nullptr, enc_emb, inp, SS, SS, EE,
        enc_Wx, G3, enc_b, gxe, BB * SS, G3, EE);

    // 2) Decoder xt-part gx (tf32 tensor path)
    gemm_tf32<<<dim3(G3 / 128, (BB * TD + 127) / 128), 128>>>(
        nullptr, dec_emb, targ, TD, SS, EE,
        dec_Wx + (size_t)UU * G3, G3, dec_b, gxd, BB * TD, G3, EE);

    // 3) Encoder recurrence: persistent TENSOR kernel (Dekker-split tf32)
    enc_persistent<<<ENC_BLOCKS, ENC_THREADS, ENC_SMEM_BYTES>>>(
        gxe, enc_Wh, enc_b + G3, enc_out, &bar[0], &bar[1]);

    // 4) P = enc_out @ dec_Wx[:U]   (tf32 tensor path)
    gemm_tf32<<<dim3(G3 / 128, (BB * SS + 127) / 128), 128>>>(
        enc_out, nullptr, nullptr, 1, 1, UU,
        dec_Wx, G3, nullptr, P, BB * SS, G3, UU);

    // 5) Decoder recurrence: ONE persistent kernel (batch-parallel)
    dec_persistent<<<BB, 256, DEC_SMEM_BYTES>>>(
        enc_out, P, gxd, dec_b + G3, hdec);

    // 6) Batched output projection (tf32 tensor path)
    gemm_tf32<<<dim3(VV / 128, (BB * TD + 127) / 128), 128>>>(
        hdec, nullptr, nullptr, 1, 1, UU,
        fc_W, VV, fc_b, out, BB * TD, VV, UU);
}